// round 11
// baseline (speedup 1.0000x reference)
#include <cuda_runtime.h>
#include <cstddef>

// Problem constants (reference: B=64, NV=8192, NF=16384, N_DISCRETE=128)
#define NVERT   8192
#define NFACE   16384
#define NB      64
#define ROWL    (NFACE * 10 + 1)            // 163841 tokens per batch row
#define THREADS 256
#define FPC     1024                        // faces per CTA
#define ITERS   (FPC / THREADS)             // 4

static const size_t L1SZ      = (size_t)NB * ROWL;          // input_ids elems
static const size_t OFF_ATT   = L1SZ;                        // attention_mask
static const size_t OFF_CODES = 2 * L1SZ;                    // codes
static const size_t CSZ       = (size_t)NB * NFACE * 9;
static const size_t OFF_DISC  = OFF_CODES + CSZ;             // discrete_face_coords
static const size_t OFF_RECON = OFF_DISC + CSZ;              // recon_faces

__device__ __forceinline__ int quant(float t) {
    // bit-exact vs reference: (t-LO)/(HI-LO)*128 - 0.5 == (t+1)*64 - 0.5
    float r = rintf((t + 1.0f) * 64.0f - 0.5f);   // jnp.round == rint (half-even)
    return (int)fminf(fmaxf(r, 0.0f), 127.0f);
}
__device__ __forceinline__ unsigned int pack3(float x, float y, float z) {
    return (unsigned int)quant(x)
         | ((unsigned int)quant(y) << 8)
         | ((unsigned int)quant(z) << 16);
}

// ---- single fused kernel: in-CTA vertex quantize + tokenize ----
__global__ void __launch_bounds__(THREADS)
k_fused(const float* __restrict__ verts,
        const int*   __restrict__ faces,
        float*       __restrict__ out) {
    __shared__ unsigned int s_tab[NVERT];           // 32 KB packed codes
    __shared__ float        s_ids[2][2576];         // 2x (2560 + shift pad)
    __shared__ float        s_cod[2][THREADS * 9];  // 2x stride-9 staging

    const int t   = threadIdx.x;
    const int gf0 = blockIdx.x * FPC;               // first face of CTA
    const int b   = gf0 >> 14;                      // batch (FPC divides NFACE)

    // ids-run alignment residues: addr(D) mod 4 floats = (b+1)&3
    const int d = (b + 1) & 3;                      // misalignment / tail count
    const int h = (4 - d) & 3;                      // scalar head count
    const int o = d;                                // smem shift => o+h in {0,4}
    const int nv4 = (2560 - h - d) >> 2;            // aligned float4 count

    // ---- build this batch's packed vertex-code table in smem ----
    // 4 vertices = 12 floats = 3 float4 per group; batch base is 16B-aligned
    // (b * 98304 floats). DRAM-read once per batch, L2-hit for sibling CTAs.
    {
        const float4* vsrc = (const float4*)(verts + (size_t)b * NVERT * 3);
        uint4* tdst = (uint4*)s_tab;
#pragma unroll
        for (int i = 0; i < (NVERT / 4) / THREADS; i++) {   // 8 groups/thread
            int g = t + i * THREADS;                // vertex group (4 verts)
            float4 a0 = __ldg(vsrc + 3 * g + 0);    // v0.xyz v1.x
            float4 a1 = __ldg(vsrc + 3 * g + 1);    // v1.yz  v2.xy
            float4 a2 = __ldg(vsrc + 3 * g + 2);    // v2.z   v3.xyz
            uint4 pk;
            pk.x = pack3(a0.x, a0.y, a0.z);
            pk.y = pack3(a0.w, a1.x, a1.y);
            pk.z = pack3(a1.z, a1.w, a2.x);
            pk.w = pack3(a2.y, a2.z, a2.w);
            tdst[g] = pk;                           // STS.128, 16B-aligned
        }
    }
    __syncthreads();

#pragma unroll
    for (int it = 0; it < ITERS; ++it) {
        const int p = it & 1;                        // ping-pong buffer
        const int f = gf0 + it * THREADS + t;        // global face id

        const int* fp = faces + (size_t)f * 3;
        unsigned int pk0 = s_tab[__ldg(fp + 0)];     // 3 scattered LDS.32
        unsigned int pk1 = s_tab[__ldg(fp + 1)];
        unsigned int pk2 = s_tab[__ldg(fp + 2)];

        float c[9];
        c[0] = (float)( pk0        & 0xFF);
        c[1] = (float)((pk0 >>  8) & 0xFF);
        c[2] = (float)((pk0 >> 16) & 0xFF);
        c[3] = (float)( pk1        & 0xFF);
        c[4] = (float)((pk1 >>  8) & 0xFF);
        c[5] = (float)((pk1 >> 16) & 0xFF);
        c[6] = (float)( pk2        & 0xFF);
        c[7] = (float)((pk2 >>  8) & 0xFF);
        c[8] = (float)((pk2 >> 16) & 0xFF);

#pragma unroll
        for (int k = 0; k < 9; k++) {
            s_ids[p][o + t * 10 + k] = c[k];         // 2-way conflict (stride 10)
            s_cod[p][t * 9 + k]      = c[k];         // conflict-free
        }
        // trailing separator; very last face of the row gets the final PAD (-1)
        s_ids[p][o + t * 10 + 9] =
            ((f & (NFACE - 1)) == (NFACE - 1)) ? -1.0f : 128.0f;
        __syncthreads();                             // single barrier per iter

        // ---- input_ids: aligned STG.128 middle + scalar fringe ----
        const int lf0 = (gf0 & (NFACE - 1)) + it * THREADS;
        float* D = out + (size_t)b * ROWL + 1 + (size_t)lf0 * 10;  // 2560 floats
        if (t < h) __stcs(D + t, s_ids[p][o + t]);
        if (t < d) __stcs(D + 2560 - d + t, s_ids[p][o + 2560 - d + t]);
        const float4* sv = (const float4*)(&s_ids[p][0] + o + h);  // 16B-aligned
        float4* Dv = (float4*)(D + h);
#pragma unroll
        for (int i = 0; i < 3; i++) {                // up to 640 float4s
            int idx = t + i * THREADS;
            if (idx < nv4) __stcs(Dv + idx, sv[idx]);
        }

        // ---- codes + discrete (identical payload): STG.128 from stride-9 ----
        const size_t cb = (size_t)(gf0 + it * THREADS) * 9;   // 16B-aligned
        const float4* cs = (const float4*)&s_cod[p][0];
        float4* d1 = (float4*)(out + OFF_CODES + cb);
        float4* d2 = (float4*)(out + OFF_DISC  + cb);
#pragma unroll
        for (int i = 0; i < 3; i++) {                // 576 float4s, 256 threads
            int idx = t + i * THREADS;
            if (idx < (THREADS * 9) / 4) {
                float4 v = cs[idx];
                __stcs(d1 + idx, v);
                __stcs(d2 + idx, v);
            }
        }

        // ---- per-batch extras from registers ----
        if ((f & (NFACE - 1)) == 0) {                // face 0 of batch b
            out[(size_t)b * ROWL] = -1.0f;           // leading PAD
            float* r = out + OFF_RECON + (size_t)b * 9;
#pragma unroll
            for (int k = 0; k < 9; k++)
                r[k] = (c[k] + 0.5f) * (1.0f / 64.0f) - 1.0f;
        }
        // no second barrier: next iter writes the other buffer; the single
        // barrier per iter guarantees all reads of buffer p finished before
        // any warp reaches iter it+2's stores to buffer p again.
    }

    // ---- attention_mask = 1.0: grid-stride float4 streaming fill ----
    {
        float4* dm = (float4*)(out + OFF_ATT);
        const float4 one = make_float4(1.0f, 1.0f, 1.0f, 1.0f);
        const size_t n4 = L1SZ / 4;
        for (size_t i = (size_t)blockIdx.x * THREADS + t; i < n4;
             i += (size_t)gridDim.x * THREADS)
            __stcs(dm + i, one);
    }
}

extern "C" void kernel_launch(void* const* d_in, const int* in_sizes, int n_in,
                              void* d_out, int out_size) {
    const float* verts = (const float*)d_in[0];
    const int*   faces = (const int*)d_in[1];
    float*       out   = (float*)d_out;

    k_fused<<<(NB * NFACE) / FPC, THREADS>>>(verts, faces, out);   // 1024 blocks
}

// round 12
// speedup vs baseline: 1.1559x; 1.1559x over previous
#include <cuda_runtime.h>
#include <cstddef>

// Problem constants (reference: B=64, NV=8192, NF=16384, N_DISCRETE=128)
#define NVERT   8192
#define NFACE   16384
#define NB      64
#define ROWL    (NFACE * 10 + 1)            // 163841 tokens per batch row
#define THREADS 256
#define FPC     1024                        // faces per CTA
#define ITERS   (FPC / THREADS)             // 4

static const size_t L1SZ      = (size_t)NB * ROWL;          // input_ids elems
static const size_t OFF_ATT   = L1SZ;                        // attention_mask
static const size_t OFF_CODES = 2 * L1SZ;                    // codes
static const size_t CSZ       = (size_t)NB * NFACE * 9;
static const size_t OFF_DISC  = OFF_CODES + CSZ;             // discrete_face_coords
static const size_t OFF_RECON = OFF_DISC + CSZ;              // recon_faces

// packed per-vertex codes: c0 | c1<<8 | c2<<16  (2 MB static scratch)
__device__ unsigned int g_vcode[NB * NVERT];

__device__ __forceinline__ int quant(float t) {
    // bit-exact vs reference: (t-LO)/(HI-LO)*128 - 0.5 == (t+1)*64 - 0.5
    float r = rintf((t + 1.0f) * 64.0f - 0.5f);   // jnp.round == rint (half-even)
    return (int)fminf(fmaxf(r, 0.0f), 127.0f);
}
__device__ __forceinline__ unsigned int pack3(float x, float y, float z) {
    return (unsigned int)quant(x)
         | ((unsigned int)quant(y) << 8)
         | ((unsigned int)quant(z) << 16);
}

// ---- pre-pass: quantize+pack 4 vertices/thread, fully vectorized ----
__global__ void k_pre(const float* __restrict__ verts) {
    const int g = blockIdx.x * blockDim.x + threadIdx.x;  // vertex group of 4
    const float4* vsrc = (const float4*)verts;            // 16B-aligned base
    float4 a0 = __ldg(vsrc + 3 * g + 0);    // v0.xyz v1.x
    float4 a1 = __ldg(vsrc + 3 * g + 1);    // v1.yz  v2.xy
    float4 a2 = __ldg(vsrc + 3 * g + 2);    // v2.z   v3.xyz
    uint4 pk;
    pk.x = pack3(a0.x, a0.y, a0.z);
    pk.y = pack3(a0.w, a1.x, a1.y);
    pk.z = pack3(a1.z, a1.w, a2.x);
    pk.w = pack3(a2.y, a2.z, a2.w);
    ((uint4*)g_vcode)[g] = pk;               // STG.128
}

// ---- fused tokenizer: smem table + double-buffered staging, stcs stores ----
__global__ void __launch_bounds__(THREADS)
k_fused(const int* __restrict__ faces, float* __restrict__ out) {
    __shared__ unsigned int s_tab[NVERT];           // 32 KB packed codes
    __shared__ float        s_ids[2][2576];         // 2x (2560 + shift pad)
    __shared__ float        s_cod[2][THREADS * 9];  // 2x stride-9 staging

    const int t   = threadIdx.x;
    const int gf0 = blockIdx.x * FPC;               // first face of CTA
    const int b   = gf0 >> 14;                      // batch (FPC divides NFACE)

    // ids-run alignment residues: addr(D) mod 4 floats = (b+1)&3
    const int d = (b + 1) & 3;                      // misalignment / tail count
    const int h = (4 - d) & 3;                      // scalar head count
    const int o = d;                                // smem shift => o+h in {0,4}
    const int nv4 = (2560 - h - d) >> 2;            // aligned float4 count

    // stage this batch's packed vertex table: 2048 uint4, coalesced
    {
        const uint4* src = (const uint4*)(g_vcode + (size_t)b * NVERT);
        uint4* dst = (uint4*)s_tab;
#pragma unroll
        for (int i = 0; i < (NVERT / 4) / THREADS; i++)   // 8 per thread
            dst[t + i * THREADS] = __ldg(src + t + i * THREADS);
    }
    __syncthreads();

#pragma unroll
    for (int it = 0; it < ITERS; ++it) {
        const int p = it & 1;                        // ping-pong buffer
        const int f = gf0 + it * THREADS + t;        // global face id

        const int* fp = faces + (size_t)f * 3;
        unsigned int pk0 = s_tab[__ldg(fp + 0)];     // 3 scattered LDS.32
        unsigned int pk1 = s_tab[__ldg(fp + 1)];
        unsigned int pk2 = s_tab[__ldg(fp + 2)];

        float c[9];
        c[0] = (float)( pk0        & 0xFF);
        c[1] = (float)((pk0 >>  8) & 0xFF);
        c[2] = (float)((pk0 >> 16) & 0xFF);
        c[3] = (float)( pk1        & 0xFF);
        c[4] = (float)((pk1 >>  8) & 0xFF);
        c[5] = (float)((pk1 >> 16) & 0xFF);
        c[6] = (float)( pk2        & 0xFF);
        c[7] = (float)((pk2 >>  8) & 0xFF);
        c[8] = (float)((pk2 >> 16) & 0xFF);

#pragma unroll
        for (int k = 0; k < 9; k++) {
            s_ids[p][o + t * 10 + k] = c[k];         // 2-way conflict (stride 10)
            s_cod[p][t * 9 + k]      = c[k];         // conflict-free
        }
        // trailing separator; very last face of the row gets the final PAD (-1)
        s_ids[p][o + t * 10 + 9] =
            ((f & (NFACE - 1)) == (NFACE - 1)) ? -1.0f : 128.0f;
        __syncthreads();                             // single barrier per iter

        // ---- input_ids: aligned STG.128 middle + scalar fringe ----
        const int lf0 = (gf0 & (NFACE - 1)) + it * THREADS;
        float* D = out + (size_t)b * ROWL + 1 + (size_t)lf0 * 10;  // 2560 floats
        if (t < h) __stcs(D + t, s_ids[p][o + t]);
        if (t < d) __stcs(D + 2560 - d + t, s_ids[p][o + 2560 - d + t]);
        const float4* sv = (const float4*)(&s_ids[p][0] + o + h);  // 16B-aligned
        float4* Dv = (float4*)(D + h);
#pragma unroll
        for (int i = 0; i < 3; i++) {                // up to 640 float4s
            int idx = t + i * THREADS;
            if (idx < nv4) __stcs(Dv + idx, sv[idx]);
        }

        // ---- codes + discrete (identical payload): STG.128 from stride-9 ----
        const size_t cb = (size_t)(gf0 + it * THREADS) * 9;   // 16B-aligned
        const float4* cs = (const float4*)&s_cod[p][0];
        float4* d1 = (float4*)(out + OFF_CODES + cb);
        float4* d2 = (float4*)(out + OFF_DISC  + cb);
#pragma unroll
        for (int i = 0; i < 3; i++) {                // 576 float4s, 256 threads
            int idx = t + i * THREADS;
            if (idx < (THREADS * 9) / 4) {
                float4 v = cs[idx];
                __stcs(d1 + idx, v);
                __stcs(d2 + idx, v);
            }
        }

        // ---- per-batch extras from registers ----
        if ((f & (NFACE - 1)) == 0) {                // face 0 of batch b
            out[(size_t)b * ROWL] = -1.0f;           // leading PAD
            float* r = out + OFF_RECON + (size_t)b * 9;
#pragma unroll
            for (int k = 0; k < 9; k++)
                r[k] = (c[k] + 0.5f) * (1.0f / 64.0f) - 1.0f;
        }
        // no second barrier: next iter writes the other buffer; the single
        // barrier per iter guarantees all reads of buffer p finished before
        // any warp reaches iter it+2's stores to buffer p again.
    }

    // ---- attention_mask = 1.0: grid-stride float4 streaming fill ----
    {
        float4* dm = (float4*)(out + OFF_ATT);
        const float4 one = make_float4(1.0f, 1.0f, 1.0f, 1.0f);
        const size_t n4 = L1SZ / 4;
        for (size_t i = (size_t)blockIdx.x * THREADS + t; i < n4;
             i += (size_t)gridDim.x * THREADS)
            __stcs(dm + i, one);
    }
}

extern "C" void kernel_launch(void* const* d_in, const int* in_sizes, int n_in,
                              void* d_out, int out_size) {
    const float* verts = (const float*)d_in[0];
    const int*   faces = (const int*)d_in[1];
    float*       out   = (float*)d_out;

    k_pre  <<<(NB * NVERT / 4) / 256, 256>>>(verts);         // 512 blocks
    k_fused<<<(NB * NFACE) / FPC, THREADS>>>(faces, out);    // 1024 blocks
}